// round 12
// baseline (speedup 1.0000x reference)
#include <cuda_runtime.h>

#define BB 32
#define NN 1024
#define HH 16
#define AA 49
#define LOG2E 1.4426950408889634f

__device__ __forceinline__ float fast_exp2(float x) {
    float y;
    asm("ex2.approx.ftz.f32 %0, %1;" : "=f"(y) : "f"(x));
    return y;
}
__device__ __forceinline__ unsigned long long dup2(float e) {
    unsigned long long r;
    asm("mov.b64 %0, {%1, %1};" : "=l"(r) : "f"(e));
    return r;
}
__device__ __forceinline__ void fma2(unsigned long long& acc, unsigned long long a, unsigned long long b) {
    asm("fma.rn.f32x2 %0, %1, %2, %3;" : "=l"(acc) : "l"(a), "l"(b), "l"(acc));
}
__device__ __forceinline__ void unpack2(unsigned long long v, float& lo, float& hi) {
    asm("mov.b64 {%0, %1}, %2;" : "=f"(lo), "=f"(hi) : "l"(v));
}

// ---------------- scratch ----------------
__device__ float  g_Aq[4*1024];
__device__ float  g_Ak[4*1024];
__device__ float  g_Av[4*1024];
__device__ float  g_M1[256];
__device__ float  g_M2[256];
__device__ float  g_G [192];
__device__ float  g_Gb[3];
__device__ float  g_T4[36];
__device__ float  g_Db[3];
__device__ float4 g_qa4[BB*AA];
__device__ float4 g_W[BB*HH*AA];

// ---------------- P1: effective weights + Q pooling ----------------
__global__ void k_pre1(const float* __restrict__ Q,
                       const float* __restrict__ wvel, const float* __restrict__ bvel,
                       const float* __restrict__ winit, const float* __restrict__ binit,
                       const float* __restrict__ wq, const float* __restrict__ bq,
                       const float* __restrict__ wk, const float* __restrict__ bk,
                       const float* __restrict__ wv, const float* __restrict__ bv)
{
    int blk = blockIdx.x, tid = threadIdx.x;
    if (blk < 96) {
        int mat = blk / 32, ctile = blk % 32;
        const float *L, *Lb, *R, *Badd; float* Out;
        if (mat == 0)      { L = wvel;  Lb = bvel;  R = wq; Badd = bq; Out = g_Aq; }
        else if (mat == 1) { L = winit; Lb = binit; R = wk; Badd = bk; Out = g_Ak; }
        else               { L = winit; Lb = binit; R = wv; Badd = bv; Out = g_Av; }
        int cl = tid & 31, mc = tid >> 5;
        int c  = ctile * 32 + cl;
        float a0 = 0.f, a1 = 0.f, a2 = 0.f, a3 = 0.f;
        int m0 = mc * 128;
        #pragma unroll 8
        for (int m = m0; m < m0 + 128; ++m) {
            float r = __ldg(&R[m * 1024 + c]);
            a0 = fmaf(__ldg(&L[m]),        r, a0);
            a1 = fmaf(__ldg(&L[1024 + m]), r, a1);
            a2 = fmaf(__ldg(&L[2048 + m]), r, a2);
            a3 = fmaf(__ldg(&Lb[m]),       r, a3);
        }
        __shared__ float red[8][32][4];
        red[mc][cl][0] = a0; red[mc][cl][1] = a1; red[mc][cl][2] = a2; red[mc][cl][3] = a3;
        __syncthreads();
        if (tid < 32) {
            float s0 = 0.f, s1 = 0.f, s2 = 0.f, s3 = 0.f;
            #pragma unroll
            for (int q = 0; q < 8; ++q) {
                s0 += red[q][tid][0]; s1 += red[q][tid][1];
                s2 += red[q][tid][2]; s3 += red[q][tid][3];
            }
            int cc = ctile * 32 + tid;
            Out[cc]          = s0;
            Out[1024 + cc]   = s1;
            Out[2048 + cc]   = s2;
            Out[3072 + cc]   = s3 + __ldg(&Badd[cc]);
        }
    } else {
        int task = (blk - 96) * 256 + tid;
        if (task < BB * AA) {
            int b = task / AA, a = task % AA;
            int s = (a * NN) / AA, e = ((a + 1) * NN + AA - 1) / AA;
            float x = 0.f, y = 0.f, z = 0.f;
            const float* Qb = Q + b * 3072;
            for (int m = s; m < e; ++m) {
                x += __ldg(&Qb[m * 3]);
                y += __ldg(&Qb[m * 3 + 1]);
                z += __ldg(&Qb[m * 3 + 2]);
            }
            float inv = 1.f / (float)(e - s);
            g_qa4[b * AA + a] = make_float4(x * inv, y * inv, z * inv, 1.f);
        }
    }
}

// ---------------- P2: tiny fused tensors (4 blocks: M1 | M2 | G+Gb | T4+Db) ----------------
__global__ void k_pre2(const float* __restrict__ wproj, const float* __restrict__ dwcw,
                       const float* __restrict__ dwcb)
{
    int blk = blockIdx.x, tid = threadIdx.x;
    if (blk == 0 || blk == 1) {
        int h = tid >> 4, i = (tid >> 2) & 3, j = tid & 3;
        const float* X = g_Aq;
        const float* Y = (blk == 1) ? g_Aq : g_Ak;
        float s = 0.f;
        #pragma unroll 8
        for (int d = 0; d < 64; ++d)
            s = fmaf(X[i * 1024 + h * 64 + d], Y[j * 1024 + h * 64 + d], s);
        ((blk == 1) ? g_M2 : g_M1)[h * 16 + i * 4 + j] = s * LOG2E;
    } else if (blk == 2) {
        __shared__ float sG[192];
        if (tid < 192) {
            int h = tid / 12, r = tid % 12, i = r / 3, j = r % 3;
            float s = 0.f;
            #pragma unroll 8
            for (int d = 0; d < 64; ++d) {
                int c = h * 64 + d;
                s = fmaf(g_Av[i * 1024 + c], __ldg(&wproj[c * 3 + j]), s);
            }
            g_G[tid] = s;
            sG[tid] = s;
        }
        __syncthreads();
        if (tid < 3) {
            float s = 0.f;
            for (int h = 0; h < HH; ++h) s += sG[h * 12 + 9 + tid];
            g_Gb[tid] = s;
        }
    } else {
        __shared__ float tpD[36][16];
        __shared__ float tpE[3][16];
        for (int t = tid; t < 624; t += 256) {
            if (t < 576) {
                int t36 = t % 36, chunk = t / 36;
                int k = t36 / 9, rr = t36 % 9, tt = rr / 3, j = rr % 3;
                float s = 0.f;
                int c0 = chunk * 64;
                #pragma unroll 4
                for (int c = c0; c < c0 + 64; ++c)
                    s = fmaf(g_Av[k * 1024 + c],
                             __ldg(&dwcw[c * 9 + tt * 3 + 1]) * __ldg(&wproj[c * 3 + j]), s);
                tpD[t36][chunk] = s;
            } else {
                int e = t - 576; int j = e % 3, chunk = e / 3;
                float s = 0.f; int c0 = chunk * 64;
                #pragma unroll 4
                for (int c = c0; c < c0 + 64; ++c)
                    s = fmaf(__ldg(&dwcb[c]), __ldg(&wproj[c * 3 + j]), s);
                tpE[j][chunk] = s;
            }
        }
        __syncthreads();
        if (tid < 36) { float s = 0.f; for (int q = 0; q < 16; ++q) s += tpD[tid][q]; g_T4[tid] = s; }
        if (tid >= 64 && tid < 67) {
            int j = tid - 64; float s = 0.f;
            for (int q = 0; q < 16; ++q) s += tpE[j][q];
            g_Db[j] = s;
        }
    }
}

// ---------------- S3 core: NCH chains per warp, a = warp + 16*j ----------------
template<int NCH>
__device__ __forceinline__ void agg_run(int warp, int lane, int b, int h,
                                        const float4* qa4s, const float* M1s, const float* Gs,
                                        const float* bias1, const float4* k4s, const ulonglong2* vp)
{
    float u0[NCH], u1[NCH], u2[NCH];
    unsigned long long aXY[NCH], aZS[NCH];
    #pragma unroll
    for (int j = 0; j < NCH; ++j) {
        float4 qa = qa4s[warp + 16 * j];
        u0[j] = qa.x * M1s[0] + qa.y * M1s[4] + qa.z * M1s[8]  + M1s[12];
        u1[j] = qa.x * M1s[1] + qa.y * M1s[5] + qa.z * M1s[9]  + M1s[13];
        u2[j] = qa.x * M1s[2] + qa.y * M1s[6] + qa.z * M1s[10] + M1s[14];
        aXY[j] = 0ull; aZS[j] = 0ull;
    }
    const float* bbase = bias1 + warp * NN + lane;

    float pA[NCH], pB[NCH];
    #pragma unroll
    for (int j = 0; j < NCH; ++j) pA[j] = __ldg(bbase + j * 16 * NN);
    #pragma unroll
    for (int j = 0; j < NCH; ++j) pB[j] = __ldg(bbase + j * 16 * NN + 32);

    for (int i = 0; i < 32; i += 2) {
        {
            int n = lane + 32 * i;
            float4 k4 = k4s[n];
            ulonglong2 vv = vp[n];
            #pragma unroll
            for (int j = 0; j < NCH; ++j) {
                float l = fmaf(u2[j], k4.z, pA[j] * LOG2E);
                l = fmaf(u1[j], k4.y, l);
                l = fmaf(u0[j], k4.x, l);
                unsigned long long e2 = dup2(fast_exp2(l));
                fma2(aXY[j], e2, vv.x);
                fma2(aZS[j], e2, vv.y);
            }
            if (i + 2 < 32) {
                #pragma unroll
                for (int j = 0; j < NCH; ++j)
                    pA[j] = __ldg(bbase + j * 16 * NN + (i + 2) * 32);
            }
        }
        {
            int n = lane + 32 * (i + 1);
            float4 k4 = k4s[n];
            ulonglong2 vv = vp[n];
            #pragma unroll
            for (int j = 0; j < NCH; ++j) {
                float l = fmaf(u2[j], k4.z, pB[j] * LOG2E);
                l = fmaf(u1[j], k4.y, l);
                l = fmaf(u0[j], k4.x, l);
                unsigned long long e2 = dup2(fast_exp2(l));
                fma2(aXY[j], e2, vv.x);
                fma2(aZS[j], e2, vv.y);
            }
            if (i + 3 < 32) {
                #pragma unroll
                for (int j = 0; j < NCH; ++j)
                    pB[j] = __ldg(bbase + j * 16 * NN + (i + 3) * 32);
            }
        }
    }
    #pragma unroll
    for (int j = 0; j < NCH; ++j) {
        float x, y, z, s;
        unpack2(aXY[j], x, y);
        unpack2(aZS[j], z, s);
        #pragma unroll
        for (int o = 16; o > 0; o >>= 1) {
            x += __shfl_xor_sync(0xffffffffu, x, o);
            y += __shfl_xor_sync(0xffffffffu, y, o);
            z += __shfl_xor_sync(0xffffffffu, z, o);
            s += __shfl_xor_sync(0xffffffffu, s, o);
        }
        if (lane == 0) {
            int a = warp + 16 * j;
            float inv = __fdividef(1.f, s);
            float vx = x * inv, vy = y * inv, vz = z * inv;
            float w0 = vx * Gs[0] + vy * Gs[3] + vz * Gs[6];
            float w1 = vx * Gs[1] + vy * Gs[4] + vz * Gs[7];
            float w2 = vx * Gs[2] + vy * Gs[5] + vz * Gs[8];
            g_W[(b * 16 + h) * AA + a] = make_float4(w0, w1, w2, 1.f);
        }
    }
}

// ---------------- S3: agent aggregation (16 warps; warp0: 4 chains, rest: 3) ----------------
__global__ void __launch_bounds__(512) k_agg(const float* __restrict__ K, const float* __restrict__ V,
                                             const float* __restrict__ bias1)
{
    int b = blockIdx.x >> 4, h = blockIdx.x & 15;
    __shared__ float4 k4s[NN];
    __shared__ float4 v4s[NN];
    __shared__ float4 qa4s[AA];
    __shared__ float  M1s[16];
    __shared__ float  Gs[12];
    int tid = threadIdx.x;
    float* kf = (float*)k4s; float* vf = (float*)v4s;
    const float* Kb = K + b * 3072; const float* Vb = V + b * 3072;
    for (int i = tid; i < 3072; i += 512) {
        int n = i / 3, c = i - n * 3;
        kf[n * 4 + c] = __ldg(&Kb[i]);
        vf[n * 4 + c] = __ldg(&Vb[i]);
    }
    for (int n = tid; n < NN; n += 512) { kf[n * 4 + 3] = 1.f; vf[n * 4 + 3] = 1.f; }
    if (tid < AA) qa4s[tid] = g_qa4[b * AA + tid];
    if (tid >= 64 && tid < 80) M1s[tid - 64] = g_M1[h * 16 + (tid - 64)];
    if (tid >= 96 && tid < 108) Gs[tid - 96] = g_G[h * 12 + (tid - 96)];
    __syncthreads();

    int warp = tid >> 5, lane = tid & 31;
    const ulonglong2* vp = (const ulonglong2*)v4s;
    if (warp == 0)
        agg_run<4>(warp, lane, b, h, qa4s, M1s, Gs, bias1, k4s, vp);
    else
        agg_run<3>(warp, lane, b, h, qa4s, M1s, Gs, bias1, k4s, vp);
}

// ---------------- S4: broadcast attention; warp = head, 4 tokens/lane ----------------
// b2s layout: [a][lane*4 + t] (row stride 132) so one LDS.128 fetches all 4 tokens' biases.
// sbuf is reused after the main loop for the per-head partials (24 KB < 25.9 KB).
__global__ void __launch_bounds__(512) k_bc(const float* __restrict__ Q, const float* __restrict__ V,
                                            const float* __restrict__ bias2,
                                            const float* __restrict__ bproj, float* __restrict__ out)
{
    int b = blockIdx.x >> 3, chunk = blockIdx.x & 7;
    int nbase = chunk * 128;
    __shared__ float  sbuf[AA * 132];   // phase1: bias; phase2: partX/partY/partZ (3*2048)
    __shared__ float4 qa4s[AA];
    __shared__ float4 w4s[HH * AA];
    __shared__ float  M2s[256];
    __shared__ float  T4s[36];
    int tid = threadIdx.x;
    const float* bsrc = bias2 + nbase * AA;
    for (int i = tid; i < 128 * AA; i += 512) {
        int nl = i / AA, a = i - nl * AA;
        sbuf[a * 132 + ((nl & 31) << 2) + (nl >> 5)] = __ldg(bsrc + i) * LOG2E;
    }
    for (int i = tid; i < HH * AA; i += 512) w4s[i] = g_W[b * HH * AA + i];
    if (tid < AA)  qa4s[tid] = g_qa4[b * AA + tid];
    if (tid >= 64 && tid < 320) M2s[tid - 64] = g_M2[tid - 64];
    if (tid >= 320 && tid < 356) T4s[tid - 320] = g_T4[tid - 320];
    __syncthreads();

    int h = tid >> 5, lane = tid & 31;
    const float* Qb = Q + b * 3072;
    const float* M = &M2s[h * 16];
    float u0[4], u1[4], u2[4];
    unsigned long long aXY[4], aZS[4];
    #pragma unroll
    for (int t = 0; t < 4; ++t) {
        int n = nbase + lane + 32 * t;
        float q0 = __ldg(&Qb[n * 3]), q1 = __ldg(&Qb[n * 3 + 1]), q2 = __ldg(&Qb[n * 3 + 2]);
        u0[t] = q0 * M[0] + q1 * M[4] + q2 * M[8]  + M[12];
        u1[t] = q0 * M[1] + q1 * M[5] + q2 * M[9]  + M[13];
        u2[t] = q0 * M[2] + q1 * M[6] + q2 * M[10] + M[14];
        aXY[t] = 0ull; aZS[t] = 0ull;
    }
    const ulonglong2* wp = (const ulonglong2*)&w4s[h * AA];
    #pragma unroll 7
    for (int a = 0; a < AA; ++a) {
        float4 bv = *(const float4*)&sbuf[a * 132 + (lane << 2)];
        float4 qa = qa4s[a];
        ulonglong2 wv = wp[a];
        float l0 = fmaf(u0[0], qa.x, bv.x);
        l0 = fmaf(u1[0], qa.y, l0);
        l0 = fmaf(u2[0], qa.z, l0);
        float l1 = fmaf(u0[1], qa.x, bv.y);
        l1 = fmaf(u1[1], qa.y, l1);
        l1 = fmaf(u2[1], qa.z, l1);
        float l2 = fmaf(u0[2], qa.x, bv.z);
        l2 = fmaf(u1[2], qa.y, l2);
        l2 = fmaf(u2[2], qa.z, l2);
        float l3 = fmaf(u0[3], qa.x, bv.w);
        l3 = fmaf(u1[3], qa.y, l3);
        l3 = fmaf(u2[3], qa.z, l3);
        unsigned long long e0 = dup2(fast_exp2(l0));
        unsigned long long e1 = dup2(fast_exp2(l1));
        unsigned long long e2 = dup2(fast_exp2(l2));
        unsigned long long e3 = dup2(fast_exp2(l3));
        fma2(aXY[0], e0, wv.x); fma2(aZS[0], e0, wv.y);
        fma2(aXY[1], e1, wv.x); fma2(aZS[1], e1, wv.y);
        fma2(aXY[2], e2, wv.x); fma2(aZS[2], e2, wv.y);
        fma2(aXY[3], e3, wv.x); fma2(aZS[3], e3, wv.y);
    }
    __syncthreads();   // all warps done reading sbuf-as-bias before overwrite
    float* partX = sbuf;
    float* partY = sbuf + 2048;
    float* partZ = sbuf + 4096;
    #pragma unroll
    for (int t = 0; t < 4; ++t) {
        float x, y, z, s;
        unpack2(aXY[t], x, y); unpack2(aZS[t], z, s);
        float inv = __fdividef(1.f, s);
        int idx = h * 128 + lane + 32 * t;
        partX[idx] = x * inv; partY[idx] = y * inv; partZ[idx] = z * inv;
    }
    __syncthreads();

    if (tid < 128) {
        float o0 = 0.f, o1 = 0.f, o2 = 0.f;
        #pragma unroll
        for (int hh = 0; hh < HH; ++hh) {
            o0 += partX[hh * 128 + tid];
            o1 += partY[hh * 128 + tid];
            o2 += partZ[hh * 128 + tid];
        }
        int n = nbase + tid;
        const float* Vb = V + b * 3072;
        float c0 = g_Gb[0] + g_Db[0] + __ldg(&bproj[0]);
        float c1 = g_Gb[1] + g_Db[1] + __ldg(&bproj[1]);
        float c2 = g_Gb[2] + g_Db[2] + __ldg(&bproj[2]);
        #pragma unroll
        for (int t = 0; t < 3; ++t) {
            int m = n + t - 1;
            if (m >= 0 && m < NN) {
                float v0 = __ldg(&Vb[m * 3]), v1 = __ldg(&Vb[m * 3 + 1]), v2 = __ldg(&Vb[m * 3 + 2]);
                c0 += v0 * T4s[0 * 9 + t * 3 + 0] + v1 * T4s[1 * 9 + t * 3 + 0]
                    + v2 * T4s[2 * 9 + t * 3 + 0] + T4s[3 * 9 + t * 3 + 0];
                c1 += v0 * T4s[0 * 9 + t * 3 + 1] + v1 * T4s[1 * 9 + t * 3 + 1]
                    + v2 * T4s[2 * 9 + t * 3 + 1] + T4s[3 * 9 + t * 3 + 1];
                c2 += v0 * T4s[0 * 9 + t * 3 + 2] + v1 * T4s[1 * 9 + t * 3 + 2]
                    + v2 * T4s[2 * 9 + t * 3 + 2] + T4s[3 * 9 + t * 3 + 2];
            }
        }
        out[b * 3072 + n]        = o0 + c0;
        out[b * 3072 + 1024 + n] = o1 + c1;
        out[b * 3072 + 2048 + n] = o2 + c2;
    }
}

// ---------------- launch ----------------
extern "C" void kernel_launch(void* const* d_in, const int* in_sizes, int n_in,
                              void* d_out, int out_size)
{
    const float* Q     = (const float*)d_in[0];
    const float* K     = (const float*)d_in[1];
    const float* V     = (const float*)d_in[2];
    const float* wvel  = (const float*)d_in[3];
    const float* bvel  = (const float*)d_in[4];
    const float* winit = (const float*)d_in[5];
    const float* binit = (const float*)d_in[6];
    const float* wq    = (const float*)d_in[7];
    const float* bq    = (const float*)d_in[8];
    const float* wk    = (const float*)d_in[9];
    const float* bk    = (const float*)d_in[10];
    const float* wv    = (const float*)d_in[11];
    const float* bv    = (const float*)d_in[12];
    const float* b1    = (const float*)d_in[13];
    const float* b2    = (const float*)d_in[14];
    const float* dwcw  = (const float*)d_in[15];
    const float* dwcb  = (const float*)d_in[16];
    const float* wproj = (const float*)d_in[17];
    const float* bproj = (const float*)d_in[18];
    float* out = (float*)d_out;

    k_pre1<<<103, 256>>>(Q, wvel, bvel, winit, binit, wq, bq, wk, bk, wv, bv);
    k_pre2<<<4, 256>>>(wproj, dwcw, dwcb);
    k_agg<<<512, 512>>>(K, V, b1);
    k_bc<<<256, 512>>>(Q, V, b2, bproj, out);
}

// round 13
// speedup vs baseline: 1.5094x; 1.5094x over previous
#include <cuda_runtime.h>

#define BB 32
#define NN 1024
#define HH 16
#define AA 49
#define LOG2E 1.4426950408889634f

__device__ __forceinline__ float fast_exp2(float x) {
    float y;
    asm("ex2.approx.ftz.f32 %0, %1;" : "=f"(y) : "f"(x));
    return y;
}
__device__ __forceinline__ unsigned long long dup2(float e) {
    unsigned long long r;
    asm("mov.b64 %0, {%1, %1};" : "=l"(r) : "f"(e));
    return r;
}
__device__ __forceinline__ void fma2(unsigned long long& acc, unsigned long long a, unsigned long long b) {
    asm("fma.rn.f32x2 %0, %1, %2, %3;" : "=l"(acc) : "l"(a), "l"(b), "l"(acc));
}
__device__ __forceinline__ void unpack2(unsigned long long v, float& lo, float& hi) {
    asm("mov.b64 {%0, %1}, %2;" : "=f"(lo), "=f"(hi) : "l"(v));
}

// ---------------- scratch ----------------
__device__ float  g_Aq[4*1024];
__device__ float  g_Ak[4*1024];
__device__ float  g_Av[4*1024];
__device__ float  g_M1[256];
__device__ float  g_M2[256];
__device__ float  g_G [192];
__device__ float  g_Gb[3];
__device__ float  g_T4[36];
__device__ float  g_Db[3];
__device__ float  g_b1s[AA*NN];     // bias1 * log2e
__device__ float4 g_qa4[BB*AA];
__device__ float4 g_W[BB*HH*AA];

// ---------------- P1: effective weights + bias1 prescale + Q pooling ----------------
__global__ void k_pre1(const float* __restrict__ Q,
                       const float* __restrict__ wvel, const float* __restrict__ bvel,
                       const float* __restrict__ winit, const float* __restrict__ binit,
                       const float* __restrict__ wq, const float* __restrict__ bq,
                       const float* __restrict__ wk, const float* __restrict__ bk,
                       const float* __restrict__ wv, const float* __restrict__ bv,
                       const float* __restrict__ bias1)
{
    int blk = blockIdx.x, tid = threadIdx.x;
    if (blk < 96) {
        int mat = blk / 32, ctile = blk % 32;
        const float *L, *Lb, *R, *Badd; float* Out;
        if (mat == 0)      { L = wvel;  Lb = bvel;  R = wq; Badd = bq; Out = g_Aq; }
        else if (mat == 1) { L = winit; Lb = binit; R = wk; Badd = bk; Out = g_Ak; }
        else               { L = winit; Lb = binit; R = wv; Badd = bv; Out = g_Av; }
        int cl = tid & 31, mc = tid >> 5;
        int c  = ctile * 32 + cl;
        float a0 = 0.f, a1 = 0.f, a2 = 0.f, a3 = 0.f;
        int m0 = mc * 128;
        #pragma unroll 8
        for (int m = m0; m < m0 + 128; ++m) {
            float r = __ldg(&R[m * 1024 + c]);
            a0 = fmaf(__ldg(&L[m]),        r, a0);
            a1 = fmaf(__ldg(&L[1024 + m]), r, a1);
            a2 = fmaf(__ldg(&L[2048 + m]), r, a2);
            a3 = fmaf(__ldg(&Lb[m]),       r, a3);
        }
        __shared__ float red[8][32][4];
        red[mc][cl][0] = a0; red[mc][cl][1] = a1; red[mc][cl][2] = a2; red[mc][cl][3] = a3;
        __syncthreads();
        if (tid < 32) {
            float s0 = 0.f, s1 = 0.f, s2 = 0.f, s3 = 0.f;
            #pragma unroll
            for (int q = 0; q < 8; ++q) {
                s0 += red[q][tid][0]; s1 += red[q][tid][1];
                s2 += red[q][tid][2]; s3 += red[q][tid][3];
            }
            int cc = ctile * 32 + tid;
            Out[cc]          = s0;
            Out[1024 + cc]   = s1;
            Out[2048 + cc]   = s2;
            Out[3072 + cc]   = s3 + __ldg(&Badd[cc]);
        }
    } else if (blk < 104) {
        int t = (blk - 96) * 256 + tid, stride = 8 * 256;
        for (int i = t; i < AA * NN; i += stride) g_b1s[i] = __ldg(&bias1[i]) * LOG2E;
    } else {
        int task = (blk - 104) * 256 + tid;
        if (task < BB * AA) {
            int b = task / AA, a = task % AA;
            int s = (a * NN) / AA, e = ((a + 1) * NN + AA - 1) / AA;
            float x = 0.f, y = 0.f, z = 0.f;
            const float* Qb = Q + b * 3072;
            for (int m = s; m < e; ++m) {
                x += __ldg(&Qb[m * 3]);
                y += __ldg(&Qb[m * 3 + 1]);
                z += __ldg(&Qb[m * 3 + 2]);
            }
            float inv = 1.f / (float)(e - s);
            g_qa4[b * AA + a] = make_float4(x * inv, y * inv, z * inv, 1.f);
        }
    }
}

// ---------------- P2: tiny fused tensors (4 blocks: M1 | M2 | G+Gb | T4+Db) ----------------
__global__ void k_pre2(const float* __restrict__ wproj, const float* __restrict__ dwcw,
                       const float* __restrict__ dwcb)
{
    int blk = blockIdx.x, tid = threadIdx.x;
    if (blk == 0 || blk == 1) {
        int h = tid >> 4, i = (tid >> 2) & 3, j = tid & 3;
        const float* X = g_Aq;
        const float* Y = (blk == 1) ? g_Aq : g_Ak;
        float s = 0.f;
        #pragma unroll 8
        for (int d = 0; d < 64; ++d)
            s = fmaf(X[i * 1024 + h * 64 + d], Y[j * 1024 + h * 64 + d], s);
        ((blk == 1) ? g_M2 : g_M1)[h * 16 + i * 4 + j] = s * LOG2E;
    } else if (blk == 2) {
        __shared__ float sG[192];
        if (tid < 192) {
            int h = tid / 12, r = tid % 12, i = r / 3, j = r % 3;
            float s = 0.f;
            #pragma unroll 8
            for (int d = 0; d < 64; ++d) {
                int c = h * 64 + d;
                s = fmaf(g_Av[i * 1024 + c], __ldg(&wproj[c * 3 + j]), s);
            }
            g_G[tid] = s;
            sG[tid] = s;
        }
        __syncthreads();
        if (tid < 3) {
            float s = 0.f;
            for (int h = 0; h < HH; ++h) s += sG[h * 12 + 9 + tid];
            g_Gb[tid] = s;
        }
    } else {
        __shared__ float tpD[36][16];
        __shared__ float tpE[3][16];
        for (int t = tid; t < 624; t += 256) {
            if (t < 576) {
                int t36 = t % 36, chunk = t / 36;
                int k = t36 / 9, rr = t36 % 9, tt = rr / 3, j = rr % 3;
                float s = 0.f;
                int c0 = chunk * 64;
                #pragma unroll 4
                for (int c = c0; c < c0 + 64; ++c)
                    s = fmaf(g_Av[k * 1024 + c],
                             __ldg(&dwcw[c * 9 + tt * 3 + 1]) * __ldg(&wproj[c * 3 + j]), s);
                tpD[t36][chunk] = s;
            } else {
                int e = t - 576; int j = e % 3, chunk = e / 3;
                float s = 0.f; int c0 = chunk * 64;
                #pragma unroll 4
                for (int c = c0; c < c0 + 64; ++c)
                    s = fmaf(__ldg(&dwcb[c]), __ldg(&wproj[c * 3 + j]), s);
                tpE[j][chunk] = s;
            }
        }
        __syncthreads();
        if (tid < 36) { float s = 0.f; for (int q = 0; q < 16; ++q) s += tpD[tid][q]; g_T4[tid] = s; }
        if (tid >= 64 && tid < 67) {
            int j = tid - 64; float s = 0.f;
            for (int q = 0; q < 16; ++q) s += tpE[j][q];
            g_Db[j] = s;
        }
    }
}

// ---------------- S3 core: NCH chains/warp; j<3: a=warp+16j, j==3: a=48 ----------------
template<int NCH>
__device__ __forceinline__ void agg_run(int warp, int lane, int b, int h,
                                        const float4* qa4s, const float* M1s, const float* Gs,
                                        const float4* k4s, const ulonglong2* vp)
{
    float u0[NCH], u1[NCH], u2[NCH];
    unsigned long long aXY[NCH], aZS[NCH];
    #pragma unroll
    for (int j = 0; j < NCH; ++j) {
        int a = (j < 3) ? (warp + 16 * j) : 48;
        float4 qa = qa4s[a];
        u0[j] = qa.x * M1s[0] + qa.y * M1s[4] + qa.z * M1s[8]  + M1s[12];
        u1[j] = qa.x * M1s[1] + qa.y * M1s[5] + qa.z * M1s[9]  + M1s[13];
        u2[j] = qa.x * M1s[2] + qa.y * M1s[6] + qa.z * M1s[10] + M1s[14];
        aXY[j] = 0ull; aZS[j] = 0ull;
    }
    const float* bbase = g_b1s + warp * NN + lane;   // rows warp+16j for j<3
    const float* bex   = g_b1s + 48 * NN + lane;     // row 48 (j==3)

    float pA[NCH], pB[NCH];
    #pragma unroll
    for (int j = 0; j < NCH; ++j) pA[j] = __ldg(((j < 3) ? bbase + j * 16 * NN : bex));
    #pragma unroll
    for (int j = 0; j < NCH; ++j) pB[j] = __ldg(((j < 3) ? bbase + j * 16 * NN : bex) + 32);

    for (int i = 0; i < 32; i += 2) {
        {
            int n = lane + 32 * i;
            float4 k4 = k4s[n];
            ulonglong2 vv = vp[n];
            #pragma unroll
            for (int j = 0; j < NCH; ++j) {
                float l = fmaf(u2[j], k4.z, pA[j]);
                l = fmaf(u1[j], k4.y, l);
                l = fmaf(u0[j], k4.x, l);
                unsigned long long e2 = dup2(fast_exp2(l));
                fma2(aXY[j], e2, vv.x);
                fma2(aZS[j], e2, vv.y);
            }
            if (i + 2 < 32) {
                #pragma unroll
                for (int j = 0; j < NCH; ++j)
                    pA[j] = __ldg(((j < 3) ? bbase + j * 16 * NN : bex) + (i + 2) * 32);
            }
        }
        {
            int n = lane + 32 * (i + 1);
            float4 k4 = k4s[n];
            ulonglong2 vv = vp[n];
            #pragma unroll
            for (int j = 0; j < NCH; ++j) {
                float l = fmaf(u2[j], k4.z, pB[j]);
                l = fmaf(u1[j], k4.y, l);
                l = fmaf(u0[j], k4.x, l);
                unsigned long long e2 = dup2(fast_exp2(l));
                fma2(aXY[j], e2, vv.x);
                fma2(aZS[j], e2, vv.y);
            }
            if (i + 3 < 32) {
                #pragma unroll
                for (int j = 0; j < NCH; ++j)
                    pB[j] = __ldg(((j < 3) ? bbase + j * 16 * NN : bex) + (i + 3) * 32);
            }
        }
    }
    #pragma unroll
    for (int j = 0; j < NCH; ++j) {
        float x, y, z, s;
        unpack2(aXY[j], x, y);
        unpack2(aZS[j], z, s);
        #pragma unroll
        for (int o = 16; o > 0; o >>= 1) {
            x += __shfl_xor_sync(0xffffffffu, x, o);
            y += __shfl_xor_sync(0xffffffffu, y, o);
            z += __shfl_xor_sync(0xffffffffu, z, o);
            s += __shfl_xor_sync(0xffffffffu, s, o);
        }
        if (lane == 0) {
            int a = (j < 3) ? (warp + 16 * j) : 48;
            float inv = __fdividef(1.f, s);
            float vx = x * inv, vy = y * inv, vz = z * inv;
            float w0 = vx * Gs[0] + vy * Gs[3] + vz * Gs[6];
            float w1 = vx * Gs[1] + vy * Gs[4] + vz * Gs[7];
            float w2 = vx * Gs[2] + vy * Gs[5] + vz * Gs[8];
            g_W[(b * 16 + h) * AA + a] = make_float4(w0, w1, w2, 1.f);
        }
    }
}

// ---------------- S3: agent aggregation (2 heads/block; extra agent rotates) ----------------
__global__ void __launch_bounds__(512) k_agg(const float* __restrict__ K, const float* __restrict__ V)
{
    int b = blockIdx.x >> 3, hp = blockIdx.x & 7;
    __shared__ float4 k4s[NN];
    __shared__ float4 v4s[NN];
    __shared__ float4 qa4s[AA];
    __shared__ float  M1s[16];
    __shared__ float  Gs[12];
    int tid = threadIdx.x;
    float* kf = (float*)k4s; float* vf = (float*)v4s;
    const float* Kb = K + b * 3072; const float* Vb = V + b * 3072;
    for (int i = tid; i < 3072; i += 512) {
        int n = i / 3, c = i - n * 3;
        kf[n * 4 + c] = __ldg(&Kb[i]);
        vf[n * 4 + c] = __ldg(&Vb[i]);
    }
    for (int n = tid; n < NN; n += 512) { kf[n * 4 + 3] = 1.f; vf[n * 4 + 3] = 1.f; }
    if (tid < AA) qa4s[tid] = g_qa4[b * AA + tid];
    __syncthreads();

    int warp = tid >> 5, lane = tid & 31;
    const ulonglong2* vp = (const ulonglong2*)v4s;

    #pragma unroll
    for (int pass = 0; pass < 2; ++pass) {
        int h = hp + 8 * pass;
        if (pass) __syncthreads();           // previous pass done before M1s/Gs overwrite
        if (tid < 16) M1s[tid] = g_M1[h * 16 + tid];
        if (tid >= 32 && tid < 44) Gs[tid - 32] = g_G[h * 12 + (tid - 32)];
        __syncthreads();
        int extraw = pass * 8;               // rotate the 49th agent's warp across passes
        if (warp == extraw)
            agg_run<4>(warp, lane, b, h, qa4s, M1s, Gs, k4s, vp);
        else
            agg_run<3>(warp, lane, b, h, qa4s, M1s, Gs, k4s, vp);
    }
}

// ---------------- S4: broadcast attention; warp = head, bias staged in smem (R11) ----------------
__global__ void __launch_bounds__(512) k_bc(const float* __restrict__ Q, const float* __restrict__ V,
                                            const float* __restrict__ bias2,
                                            const float* __restrict__ bproj, float* __restrict__ out)
{
    int b = blockIdx.x >> 4, chunk = blockIdx.x & 15;
    int nbase = chunk * 64;
    __shared__ float  b2s[64 * AA];
    __shared__ float4 qa4s[AA];
    __shared__ float4 w4s[HH * AA];
    __shared__ float  M2s[256];
    __shared__ float4 part[HH * 64];
    __shared__ float  T4s[36];
    int tid = threadIdx.x;
    const float* bsrc = bias2 + nbase * AA;
    for (int t = tid; t < 64 * AA; t += 512) b2s[t] = __ldg(bsrc + t) * LOG2E;
    for (int i = tid; i < HH * AA; i += 512) w4s[i] = g_W[b * HH * AA + i];
    if (tid < AA)  qa4s[tid] = g_qa4[b * AA + tid];
    if (tid >= 64 && tid < 320) M2s[tid - 64] = g_M2[tid - 64];
    if (tid >= 320 && tid < 356) T4s[tid - 320] = g_T4[tid - 320];
    __syncthreads();

    int h = tid >> 5, lane = tid & 31;
    int n0 = nbase + lane, n1 = n0 + 32;
    const float* Qb = Q + b * 3072;
    float p0 = __ldg(&Qb[n0 * 3]), p1 = __ldg(&Qb[n0 * 3 + 1]), p2 = __ldg(&Qb[n0 * 3 + 2]);
    float r0 = __ldg(&Qb[n1 * 3]), r1 = __ldg(&Qb[n1 * 3 + 1]), r2 = __ldg(&Qb[n1 * 3 + 2]);
    const float* M = &M2s[h * 16];
    float ua0 = p0 * M[0] + p1 * M[4] + p2 * M[8]  + M[12];
    float ua1 = p0 * M[1] + p1 * M[5] + p2 * M[9]  + M[13];
    float ua2 = p0 * M[2] + p1 * M[6] + p2 * M[10] + M[14];
    float ub0 = r0 * M[0] + r1 * M[4] + r2 * M[8]  + M[12];
    float ub1 = r0 * M[1] + r1 * M[5] + r2 * M[9]  + M[13];
    float ub2 = r0 * M[2] + r1 * M[6] + r2 * M[10] + M[14];

    unsigned long long aXY0 = 0ull, aZS0 = 0ull, aXY1 = 0ull, aZS1 = 0ull;
    const float* brow0 = &b2s[lane * AA];
    const float* brow1 = &b2s[(lane + 32) * AA];
    const ulonglong2* wp = (const ulonglong2*)&w4s[h * AA];
    #pragma unroll 7
    for (int a = 0; a < AA; ++a) {
        float4 qa = qa4s[a];
        ulonglong2 wv = wp[a];
        float bv0 = brow0[a];
        float bv1 = brow1[a];
        float l0 = fmaf(ua0, qa.x, bv0);
        l0 = fmaf(ua1, qa.y, l0);
        l0 = fmaf(ua2, qa.z, l0);
        float l1 = fmaf(ub0, qa.x, bv1);
        l1 = fmaf(ub1, qa.y, l1);
        l1 = fmaf(ub2, qa.z, l1);
        unsigned long long e0 = dup2(fast_exp2(l0));
        unsigned long long e1 = dup2(fast_exp2(l1));
        fma2(aXY0, e0, wv.x); fma2(aZS0, e0, wv.y);
        fma2(aXY1, e1, wv.x); fma2(aZS1, e1, wv.y);
    }
    {
        float x, y, z, s;
        unpack2(aXY0, x, y); unpack2(aZS0, z, s);
        float inv = __fdividef(1.f, s);
        part[h * 64 + lane] = make_float4(x * inv, y * inv, z * inv, 0.f);
        unpack2(aXY1, x, y); unpack2(aZS1, z, s);
        inv = __fdividef(1.f, s);
        part[h * 64 + lane + 32] = make_float4(x * inv, y * inv, z * inv, 0.f);
    }
    __syncthreads();

    if (tid < 64) {
        float o0 = 0.f, o1 = 0.f, o2 = 0.f;
        #pragma unroll
        for (int hh = 0; hh < HH; ++hh) {
            float4 p = part[hh * 64 + tid];
            o0 += p.x; o1 += p.y; o2 += p.z;
        }
        int n = nbase + tid;
        const float* Vb = V + b * 3072;
        float c0 = g_Gb[0] + g_Db[0] + __ldg(&bproj[0]);
        float c1 = g_Gb[1] + g_Db[1] + __ldg(&bproj[1]);
        float c2 = g_Gb[2] + g_Db[2] + __ldg(&bproj[2]);
        #pragma unroll
        for (int t = 0; t < 3; ++t) {
            int m = n + t - 1;
            if (m >= 0 && m < NN) {
                float v0 = __ldg(&Vb[m * 3]), v1 = __ldg(&Vb[m * 3 + 1]), v2 = __ldg(&Vb[m * 3 + 2]);
                c0 += v0 * T4s[0 * 9 + t * 3 + 0] + v1 * T4s[1 * 9 + t * 3 + 0]
                    + v2 * T4s[2 * 9 + t * 3 + 0] + T4s[3 * 9 + t * 3 + 0];
                c1 += v0 * T4s[0 * 9 + t * 3 + 1] + v1 * T4s[1 * 9 + t * 3 + 1]
                    + v2 * T4s[2 * 9 + t * 3 + 1] + T4s[3 * 9 + t * 3 + 1];
                c2 += v0 * T4s[0 * 9 + t * 3 + 2] + v1 * T4s[1 * 9 + t * 3 + 2]
                    + v2 * T4s[2 * 9 + t * 3 + 2] + T4s[3 * 9 + t * 3 + 2];
            }
        }
        out[b * 3072 + n]        = o0 + c0;
        out[b * 3072 + 1024 + n] = o1 + c1;
        out[b * 3072 + 2048 + n] = o2 + c2;
    }
}

// ---------------- launch ----------------
extern "C" void kernel_launch(void* const* d_in, const int* in_sizes, int n_in,
                              void* d_out, int out_size)
{
    const float* Q     = (const float*)d_in[0];
    const float* K     = (const float*)d_in[1];
    const float* V     = (const float*)d_in[2];
    const float* wvel  = (const float*)d_in[3];
    const float* bvel  = (const float*)d_in[4];
    const float* winit = (const float*)d_in[5];
    const float* binit = (const float*)d_in[6];
    const float* wq    = (const float*)d_in[7];
    const float* bq    = (const float*)d_in[8];
    const float* wk    = (const float*)d_in[9];
    const float* bk    = (const float*)d_in[10];
    const float* wv    = (const float*)d_in[11];
    const float* bv    = (const float*)d_in[12];
    const float* b1    = (const float*)d_in[13];
    const float* b2    = (const float*)d_in[14];
    const float* dwcw  = (const float*)d_in[15];
    const float* dwcb  = (const float*)d_in[16];
    const float* wproj = (const float*)d_in[17];
    const float* bproj = (const float*)d_in[18];
    float* out = (float*)d_out;

    k_pre1<<<111, 256>>>(Q, wvel, bvel, winit, binit, wq, bq, wk, bk, wv, bv, b1);
    k_pre2<<<4, 256>>>(wproj, dwcw, dwcb);
    k_agg<<<256, 512>>>(K, V);
    k_bc<<<512, 512>>>(Q, V, b2, bproj, out);
}

// round 14
// speedup vs baseline: 1.7222x; 1.1410x over previous
#include <cuda_runtime.h>

#define BB 32
#define NN 1024
#define HH 16
#define AA 49
#define LOG2E 1.4426950408889634f

__device__ __forceinline__ float fast_exp2(float x) {
    float y;
    asm("ex2.approx.ftz.f32 %0, %1;" : "=f"(y) : "f"(x));
    return y;
}
__device__ __forceinline__ unsigned long long dup2(float e) {
    unsigned long long r;
    asm("mov.b64 %0, {%1, %1};" : "=l"(r) : "f"(e));
    return r;
}
__device__ __forceinline__ void fma2(unsigned long long& acc, unsigned long long a, unsigned long long b) {
    asm("fma.rn.f32x2 %0, %1, %2, %3;" : "=l"(acc) : "l"(a), "l"(b), "l"(acc));
}
__device__ __forceinline__ void unpack2(unsigned long long v, float& lo, float& hi) {
    asm("mov.b64 {%0, %1}, %2;" : "=f"(lo), "=f"(hi) : "l"(v));
}

// ---------------- scratch ----------------
__device__ float  g_Aq[4*1024];
__device__ float  g_Ak[4*1024];
__device__ float  g_Av[4*1024];
__device__ float  g_M1[256];
__device__ float  g_M2[256];
__device__ float  g_G [192];
__device__ float  g_Gb[3];
__device__ float  g_T4[36];
__device__ float  g_Db[3];
__device__ float  g_b1s[AA*NN];     // bias1 * log2e
__device__ float4 g_qa4[BB*AA];
__device__ float4 g_W[BB*HH*AA];

// ---------------- P1: effective weights (vectorized) + bias1 prescale + Q pooling ----------------
// blocks [0,192): GEMM  — mat = blk/64, 16-column tile = blk%64
// blocks [192,200): bias1 * log2e
// blocks [200,207): Q adaptive-avg-pool
__global__ void k_pre1(const float* __restrict__ Q,
                       const float* __restrict__ wvel, const float* __restrict__ bvel,
                       const float* __restrict__ winit, const float* __restrict__ binit,
                       const float* __restrict__ wq, const float* __restrict__ bq,
                       const float* __restrict__ wk, const float* __restrict__ bk,
                       const float* __restrict__ wv, const float* __restrict__ bv,
                       const float* __restrict__ bias1)
{
    int blk = blockIdx.x, tid = threadIdx.x;
    if (blk < 192) {
        int mat = blk >> 6, ct = blk & 63;
        const float *L, *Lb, *R, *Badd; float* Out;
        if (mat == 0)      { L = wvel;  Lb = bvel;  R = wq; Badd = bq; Out = g_Aq; }
        else if (mat == 1) { L = winit; Lb = binit; R = wk; Badd = bk; Out = g_Ak; }
        else               { L = winit; Lb = binit; R = wv; Badd = bv; Out = g_Av; }
        int cthr = tid & 3, mg = tid >> 2;          // 4 col-threads x 64 m-groups
        int c0 = ct * 16 + cthr * 4;
        float a00=0.f,a01=0.f,a02=0.f,a03=0.f;
        float a10=0.f,a11=0.f,a12=0.f,a13=0.f;
        float a20=0.f,a21=0.f,a22=0.f,a23=0.f;
        float a30=0.f,a31=0.f,a32=0.f,a33=0.f;
        int m0 = mg * 16;
        #pragma unroll
        for (int i = 0; i < 16; ++i) {
            int m = m0 + i;
            float4 r = __ldg((const float4*)&R[m * 1024 + c0]);
            float l0 = __ldg(&L[m]);
            float l1 = __ldg(&L[1024 + m]);
            float l2 = __ldg(&L[2048 + m]);
            float l3 = __ldg(&Lb[m]);
            a00 = fmaf(l0, r.x, a00); a01 = fmaf(l0, r.y, a01); a02 = fmaf(l0, r.z, a02); a03 = fmaf(l0, r.w, a03);
            a10 = fmaf(l1, r.x, a10); a11 = fmaf(l1, r.y, a11); a12 = fmaf(l1, r.z, a12); a13 = fmaf(l1, r.w, a13);
            a20 = fmaf(l2, r.x, a20); a21 = fmaf(l2, r.y, a21); a22 = fmaf(l2, r.z, a22); a23 = fmaf(l2, r.w, a23);
            a30 = fmaf(l3, r.x, a30); a31 = fmaf(l3, r.y, a31); a32 = fmaf(l3, r.z, a32); a33 = fmaf(l3, r.w, a33);
        }
        __shared__ float4 red[64][4][5];    // [mg][cthr][row] (+pad)
        red[mg][cthr][0] = make_float4(a00, a01, a02, a03);
        red[mg][cthr][1] = make_float4(a10, a11, a12, a13);
        red[mg][cthr][2] = make_float4(a20, a21, a22, a23);
        red[mg][cthr][3] = make_float4(a30, a31, a32, a33);
        __syncthreads();
        if (tid < 64) {
            int i = tid >> 4, cc = tid & 15;
            float s = 0.f;
            #pragma unroll 8
            for (int g = 0; g < 64; ++g)
                s += ((const float*)&red[g][cc >> 2][i])[cc & 3];
            int c = ct * 16 + cc;
            if (i < 3) Out[i * 1024 + c] = s;
            else       Out[3072 + c]     = s + __ldg(&Badd[c]);
        }
    } else if (blk < 200) {
        int t = (blk - 192) * 256 + tid, stride = 8 * 256;
        for (int i = t; i < AA * NN; i += stride) g_b1s[i] = __ldg(&bias1[i]) * LOG2E;
    } else {
        int task = (blk - 200) * 256 + tid;
        if (task < BB * AA) {
            int b = task / AA, a = task % AA;
            int s = (a * NN) / AA, e = ((a + 1) * NN + AA - 1) / AA;
            float x = 0.f, y = 0.f, z = 0.f;
            const float* Qb = Q + b * 3072;
            for (int m = s; m < e; ++m) {
                x += __ldg(&Qb[m * 3]);
                y += __ldg(&Qb[m * 3 + 1]);
                z += __ldg(&Qb[m * 3 + 2]);
            }
            float inv = 1.f / (float)(e - s);
            g_qa4[b * AA + a] = make_float4(x * inv, y * inv, z * inv, 1.f);
        }
    }
}

// ---------------- P2: tiny fused tensors (4 blocks: M1 | M2 | G+Gb | T4+Db) ----------------
__global__ void k_pre2(const float* __restrict__ wproj, const float* __restrict__ dwcw,
                       const float* __restrict__ dwcb)
{
    int blk = blockIdx.x, tid = threadIdx.x;
    if (blk == 0 || blk == 1) {
        int h = tid >> 4, i = (tid >> 2) & 3, j = tid & 3;
        const float* X = g_Aq;
        const float* Y = (blk == 1) ? g_Aq : g_Ak;
        float s = 0.f;
        #pragma unroll 8
        for (int d = 0; d < 64; ++d)
            s = fmaf(X[i * 1024 + h * 64 + d], Y[j * 1024 + h * 64 + d], s);
        ((blk == 1) ? g_M2 : g_M1)[h * 16 + i * 4 + j] = s * LOG2E;
    } else if (blk == 2) {
        __shared__ float sG[192];
        if (tid < 192) {
            int h = tid / 12, r = tid % 12, i = r / 3, j = r % 3;
            float s = 0.f;
            #pragma unroll 8
            for (int d = 0; d < 64; ++d) {
                int c = h * 64 + d;
                s = fmaf(g_Av[i * 1024 + c], __ldg(&wproj[c * 3 + j]), s);
            }
            g_G[tid] = s;
            sG[tid] = s;
        }
        __syncthreads();
        if (tid < 3) {
            float s = 0.f;
            for (int h = 0; h < HH; ++h) s += sG[h * 12 + 9 + tid];
            g_Gb[tid] = s;
        }
    } else {
        __shared__ float tpD[36][16];
        __shared__ float tpE[3][16];
        for (int t = tid; t < 624; t += 256) {
            if (t < 576) {
                int t36 = t % 36, chunk = t / 36;
                int k = t36 / 9, rr = t36 % 9, tt = rr / 3, j = rr % 3;
                float s = 0.f;
                int c0 = chunk * 64;
                #pragma unroll 4
                for (int c = c0; c < c0 + 64; ++c)
                    s = fmaf(g_Av[k * 1024 + c],
                             __ldg(&dwcw[c * 9 + tt * 3 + 1]) * __ldg(&wproj[c * 3 + j]), s);
                tpD[t36][chunk] = s;
            } else {
                int e = t - 576; int j = e % 3, chunk = e / 3;
                float s = 0.f; int c0 = chunk * 64;
                #pragma unroll 4
                for (int c = c0; c < c0 + 64; ++c)
                    s = fmaf(__ldg(&dwcb[c]), __ldg(&wproj[c * 3 + j]), s);
                tpE[j][chunk] = s;
            }
        }
        __syncthreads();
        if (tid < 36) { float s = 0.f; for (int q = 0; q < 16; ++q) s += tpD[tid][q]; g_T4[tid] = s; }
        if (tid >= 64 && tid < 67) {
            int j = tid - 64; float s = 0.f;
            for (int q = 0; q < 16; ++q) s += tpE[j][q];
            g_Db[j] = s;
        }
    }
}

// ---------------- S3 core: NCH chains/warp; j<3: a=warp+16j, j==3: a=48 ----------------
template<int NCH>
__device__ __forceinline__ void agg_run(int warp, int lane, int b, int h,
                                        const float4* qa4s, const float* M1s, const float* Gs,
                                        const float4* k4s, const ulonglong2* vp)
{
    float u0[NCH], u1[NCH], u2[NCH];
    unsigned long long aXY[NCH], aZS[NCH];
    #pragma unroll
    for (int j = 0; j < NCH; ++j) {
        int a = (j < 3) ? (warp + 16 * j) : 48;
        float4 qa = qa4s[a];
        u0[j] = qa.x * M1s[0] + qa.y * M1s[4] + qa.z * M1s[8]  + M1s[12];
        u1[j] = qa.x * M1s[1] + qa.y * M1s[5] + qa.z * M1s[9]  + M1s[13];
        u2[j] = qa.x * M1s[2] + qa.y * M1s[6] + qa.z * M1s[10] + M1s[14];
        aXY[j] = 0ull; aZS[j] = 0ull;
    }
    const float* bbase = g_b1s + warp * NN + lane;
    const float* bex   = g_b1s + 48 * NN + lane;

    float pA[NCH], pB[NCH];
    #pragma unroll
    for (int j = 0; j < NCH; ++j) pA[j] = __ldg(((j < 3) ? bbase + j * 16 * NN : bex));
    #pragma unroll
    for (int j = 0; j < NCH; ++j) pB[j] = __ldg(((j < 3) ? bbase + j * 16 * NN : bex) + 32);

    for (int i = 0; i < 32; i += 2) {
        {
            int n = lane + 32 * i;
            float4 k4 = k4s[n];
            ulonglong2 vv = vp[n];
            #pragma unroll
            for (int j = 0; j < NCH; ++j) {
                float l = fmaf(u2[j], k4.z, pA[j]);
                l = fmaf(u1[j], k4.y, l);
                l = fmaf(u0[j], k4.x, l);
                unsigned long long e2 = dup2(fast_exp2(l));
                fma2(aXY[j], e2, vv.x);
                fma2(aZS[j], e2, vv.y);
            }
            if (i + 2 < 32) {
                #pragma unroll
                for (int j = 0; j < NCH; ++j)
                    pA[j] = __ldg(((j < 3) ? bbase + j * 16 * NN : bex) + (i + 2) * 32);
            }
        }
        {
            int n = lane + 32 * (i + 1);
            float4 k4 = k4s[n];
            ulonglong2 vv = vp[n];
            #pragma unroll
            for (int j = 0; j < NCH; ++j) {
                float l = fmaf(u2[j], k4.z, pB[j]);
                l = fmaf(u1[j], k4.y, l);
                l = fmaf(u0[j], k4.x, l);
                unsigned long long e2 = dup2(fast_exp2(l));
                fma2(aXY[j], e2, vv.x);
                fma2(aZS[j], e2, vv.y);
            }
            if (i + 3 < 32) {
                #pragma unroll
                for (int j = 0; j < NCH; ++j)
                    pB[j] = __ldg(((j < 3) ? bbase + j * 16 * NN : bex) + (i + 3) * 32);
            }
        }
    }
    #pragma unroll
    for (int j = 0; j < NCH; ++j) {
        float x, y, z, s;
        unpack2(aXY[j], x, y);
        unpack2(aZS[j], z, s);
        #pragma unroll
        for (int o = 16; o > 0; o >>= 1) {
            x += __shfl_xor_sync(0xffffffffu, x, o);
            y += __shfl_xor_sync(0xffffffffu, y, o);
            z += __shfl_xor_sync(0xffffffffu, z, o);
            s += __shfl_xor_sync(0xffffffffu, s, o);
        }
        if (lane == 0) {
            int a = (j < 3) ? (warp + 16 * j) : 48;
            float inv = __fdividef(1.f, s);
            float vx = x * inv, vy = y * inv, vz = z * inv;
            float w0 = vx * Gs[0] + vy * Gs[3] + vz * Gs[6];
            float w1 = vx * Gs[1] + vy * Gs[4] + vz * Gs[7];
            float w2 = vx * Gs[2] + vy * Gs[5] + vz * Gs[8];
            g_W[(b * 16 + h) * AA + a] = make_float4(w0, w1, w2, 1.f);
        }
    }
}

// ---------------- S3: agent aggregation (2 heads/block; extra agent rotates) ----------------
__global__ void __launch_bounds__(512) k_agg(const float* __restrict__ K, const float* __restrict__ V)
{
    int b = blockIdx.x >> 3, hp = blockIdx.x & 7;
    __shared__ float4 k4s[NN];
    __shared__ float4 v4s[NN];
    __shared__ float4 qa4s[AA];
    __shared__ float  M1s[16];
    __shared__ float  Gs[12];
    int tid = threadIdx.x;
    float* kf = (float*)k4s; float* vf = (float*)v4s;
    const float* Kb = K + b * 3072; const float* Vb = V + b * 3072;
    for (int i = tid; i < 3072; i += 512) {
        int n = i / 3, c = i - n * 3;
        kf[n * 4 + c] = __ldg(&Kb[i]);
        vf[n * 4 + c] = __ldg(&Vb[i]);
    }
    for (int n = tid; n < NN; n += 512) { kf[n * 4 + 3] = 1.f; vf[n * 4 + 3] = 1.f; }
    if (tid < AA) qa4s[tid] = g_qa4[b * AA + tid];
    __syncthreads();

    int warp = tid >> 5, lane = tid & 31;
    const ulonglong2* vp = (const ulonglong2*)v4s;

    #pragma unroll
    for (int pass = 0; pass < 2; ++pass) {
        int h = hp + 8 * pass;
        if (pass) __syncthreads();
        if (tid < 16) M1s[tid] = g_M1[h * 16 + tid];
        if (tid >= 32 && tid < 44) Gs[tid - 32] = g_G[h * 12 + (tid - 32)];
        __syncthreads();
        int extraw = pass * 8;
        if (warp == extraw)
            agg_run<4>(warp, lane, b, h, qa4s, M1s, Gs, k4s, vp);
        else
            agg_run<3>(warp, lane, b, h, qa4s, M1s, Gs, k4s, vp);
    }
}

// ---------------- S4: broadcast attention; warp = head, paired bias in smem ----------------
__global__ void __launch_bounds__(512) k_bc(const float* __restrict__ Q, const float* __restrict__ V,
                                            const float* __restrict__ bias2,
                                            const float* __restrict__ bproj, float* __restrict__ out)
{
    int b = blockIdx.x >> 4, chunk = blockIdx.x & 15;
    int nbase = chunk * 64;
    __shared__ float  b2s[AA * 66];     // [a][lane*2 + t], stride 66
    __shared__ float4 qa4s[AA];
    __shared__ float4 w4s[HH * AA];
    __shared__ float  M2s[256];
    __shared__ float4 part[HH * 64];
    __shared__ float  T4s[36];
    int tid = threadIdx.x;
    const float* bsrc = bias2 + nbase * AA;
    for (int i = tid; i < 64 * AA; i += 512) {
        int nl = i / AA, a = i - nl * AA;
        b2s[a * 66 + ((nl & 31) << 1) + (nl >> 5)] = __ldg(bsrc + i) * LOG2E;
    }
    for (int i = tid; i < HH * AA; i += 512) w4s[i] = g_W[b * HH * AA + i];
    if (tid < AA)  qa4s[tid] = g_qa4[b * AA + tid];
    if (tid >= 64 && tid < 320) M2s[tid - 64] = g_M2[tid - 64];
    if (tid >= 320 && tid < 356) T4s[tid - 320] = g_T4[tid - 320];
    __syncthreads();

    int h = tid >> 5, lane = tid & 31;
    int n0 = nbase + lane, n1 = n0 + 32;
    const float* Qb = Q + b * 3072;
    float p0 = __ldg(&Qb[n0 * 3]), p1 = __ldg(&Qb[n0 * 3 + 1]), p2 = __ldg(&Qb[n0 * 3 + 2]);
    float r0 = __ldg(&Qb[n1 * 3]), r1 = __ldg(&Qb[n1 * 3 + 1]), r2 = __ldg(&Qb[n1 * 3 + 2]);
    const float* M = &M2s[h * 16];
    float ua0 = p0 * M[0] + p1 * M[4] + p2 * M[8]  + M[12];
    float ua1 = p0 * M[1] + p1 * M[5] + p2 * M[9]  + M[13];
    float ua2 = p0 * M[2] + p1 * M[6] + p2 * M[10] + M[14];
    float ub0 = r0 * M[0] + r1 * M[4] + r2 * M[8]  + M[12];
    float ub1 = r0 * M[1] + r1 * M[5] + r2 * M[9]  + M[13];
    float ub2 = r0 * M[2] + r1 * M[6] + r2 * M[10] + M[14];

    unsigned long long aXY0 = 0ull, aZS0 = 0ull, aXY1 = 0ull, aZS1 = 0ull;
    const float* brow = &b2s[lane << 1];
    const ulonglong2* wp = (const ulonglong2*)&w4s[h * AA];
    #pragma unroll 7
    for (int a = 0; a < AA; ++a) {
        float4 qa = qa4s[a];
        ulonglong2 wv = wp[a];
        float2 bv = *(const float2*)&brow[a * 66];
        float l0 = fmaf(ua0, qa.x, bv.x);
        l0 = fmaf(ua1, qa.y, l0);
        l0 = fmaf(ua2, qa.z, l0);
        float l1 = fmaf(ub0, qa.x, bv.y);
        l1 = fmaf(ub1, qa.y, l1);
        l1 = fmaf(ub2, qa.z, l1);
        unsigned long long e0 = dup2(fast_exp2(l0));
        unsigned long long e1 = dup2(fast_exp2(l1));
        fma2(aXY0, e0, wv.x); fma2(aZS0, e0, wv.y);
        fma2(aXY1, e1, wv.x); fma2(aZS1, e1, wv.y);
    }
    {
        float x, y, z, s;
        unpack2(aXY0, x, y); unpack2(aZS0, z, s);
        float inv = __fdividef(1.f, s);
        part[h * 64 + lane] = make_float4(x * inv, y * inv, z * inv, 0.f);
        unpack2(aXY1, x, y); unpack2(aZS1, z, s);
        inv = __fdividef(1.f, s);
        part[h * 64 + lane + 32] = make_float4(x * inv, y * inv, z * inv, 0.f);
    }
    __syncthreads();

    if (tid < 64) {
        float o0 = 0.f, o1 = 0.f, o2 = 0.f;
        #pragma unroll
        for (int hh = 0; hh < HH; ++hh) {
            float4 p = part[hh * 64 + tid];
            o0 += p.x; o1 += p.y; o2 += p.z;
        }
        int n = nbase + tid;
        const float* Vb = V + b * 3072;
        float c0 = g_Gb[0] + g_Db[0] + __ldg(&bproj[0]);
        float c1 = g_Gb[1] + g_Db[1] + __ldg(&bproj[1]);
        float c2 = g_Gb[2] + g_Db[2] + __ldg(&bproj[2]);
        #pragma unroll
        for (int t = 0; t < 3; ++t) {
            int m = n + t - 1;
            if (m >= 0 && m < NN) {
                float v0 = __ldg(&Vb[m * 3]), v1 = __ldg(&Vb[m * 3 + 1]), v2 = __ldg(&Vb[m * 3 + 2]);
                c0 += v0 * T4s[0 * 9 + t * 3 + 0] + v1 * T4s[1 * 9 + t * 3 + 0]
                    + v2 * T4s[2 * 9 + t * 3 + 0] + T4s[3 * 9 + t * 3 + 0];
                c1 += v0 * T4s[0 * 9 + t * 3 + 1] + v1 * T4s[1 * 9 + t * 3 + 1]
                    + v2 * T4s[2 * 9 + t * 3 + 1] + T4s[3 * 9 + t * 3 + 1];
                c2 += v0 * T4s[0 * 9 + t * 3 + 2] + v1 * T4s[1 * 9 + t * 3 + 2]
                    + v2 * T4s[2 * 9 + t * 3 + 2] + T4s[3 * 9 + t * 3 + 2];
            }
        }
        out[b * 3072 + n]        = o0 + c0;
        out[b * 3072 + 1024 + n] = o1 + c1;
        out[b * 3072 + 2048 + n] = o2 + c2;
    }
}

// ---------------- launch ----------------
extern "C" void kernel_launch(void* const* d_in, const int* in_sizes, int n_in,
                              void* d_out, int out_size)
{
    const float* Q     = (const float*)d_in[0];
    const float* K     = (const float*)d_in[1];
    const float* V     = (const float*)d_in[2];
    const float* wvel  = (const float*)d_in[3];
    const float* bvel  = (const float*)d_in[4];
    const float* winit = (const float*)d_in[5];
    const float* binit = (const float*)d_in[6];
    const float* wq    = (const float*)d_in[7];
    const float* bq    = (const float*)d_in[8];
    const float* wk    = (const float*)d_in[9];
    const float* bk    = (const float*)d_in[10];
    const float* wv    = (const float*)d_in[11];
    const float* bv    = (const float*)d_in[12];
    const float* b1    = (const float*)d_in[13];
    const float* b2    = (const float*)d_in[14];
    const float* dwcw  = (const float*)d_in[15];
    const float* dwcb  = (const float*)d_in[16];
    const float* wproj = (const float*)d_in[17];
    const float* bproj = (const float*)d_in[18];
    float* out = (float*)d_out;

    k_pre1<<<207, 256>>>(Q, wvel, bvel, winit, binit, wq, bq, wk, bk, wv, bv, b1);
    k_pre2<<<4, 256>>>(wproj, dwcw, dwcb);
    k_agg<<<256, 512>>>(K, V);
    k_bc<<<512, 512>>>(Q, V, b2, bproj, out);
}